// round 3
// baseline (speedup 1.0000x reference)
#include <cuda_runtime.h>
#include <cstdint>

// ---------------- problem constants ----------------
#define T_TOK 8192          // B*S = 4*2048 tokens
#define H_DIM 1024
#define E_NUM 8
#define I_DIM 4096
#define NTHREADS 256

// Arch-feature dispatch: tcgen05 PTX is only legal in the sm_103a ("arch
// accelerated") device pass. In any plain compute_103/sm_103 pass we compile
// an FFMA fallback instead so ptxas never sees tcgen05 there.
#if !defined(__CUDA_ARCH__) || defined(__CUDA_ARCH_FEAT_SM103_ALL)
#define HAS_TC 1
#else
#define HAS_TC 0
#endif

// ---------------- device scratch (static, allocation-free) ----------------
__device__ int   g_count[E_NUM];
__device__ int   g_tok[E_NUM * T_TOK];
__device__ float g_wt [E_NUM * T_TOK];
__device__ float g_h  [268435456];   // E*T*I = 8*8192*4096 floats (1.07 GB)

#if HAS_TC
// ---------------- PTX helpers (sm_103a only) ----------------
__device__ __forceinline__ uint32_t smem_u32(const void* p) {
    uint32_t a;
    asm("{ .reg .u64 t; cvta.to.shared.u64 t, %1; cvt.u32.u64 %0, t; }"
        : "=r"(a) : "l"(p));
    return a;
}
__device__ __forceinline__ uint32_t elect1() {
    uint32_t p;
    asm volatile("{ .reg .pred p; elect.sync _|p, 0xFFFFFFFF; selp.b32 %0,1,0,p; }" : "=r"(p));
    return p;
}
__device__ __forceinline__ float to_tf32(float f) {
    uint32_t u;
    asm("cvt.rna.tf32.f32 %0, %1;" : "=r"(u) : "f"(f));
    return __uint_as_float(u);
}

#define SW128(x) ((x) ^ (((x) >> 3) & 0x70))

// SW128 K-major smem descriptor (Blackwell): layout=2, version=1, SBO=64, LBO=1
static constexpr uint64_t DESC_BASE =
    (2ull << 61) | (1ull << 46) | (64ull << 32) | (1ull << 16);
__device__ __forceinline__ uint64_t mkdesc(uint32_t smem_addr) {
    return DESC_BASE | ((uint64_t)(smem_addr >> 4) & 0x3FFF);
}

// idesc: D=F32(1<<4), A=TF32(2<<7), B=TF32(2<<10), N=256 (32<<17), M=128 (8<<24)
static constexpr uint32_t IDESC_TF32_N256 =
    (1u << 4) | (2u << 7) | (2u << 10) | (32u << 17) | (8u << 24);

__device__ __forceinline__ void mma_tf32(uint32_t d_tmem, uint64_t a_desc,
                                         uint64_t b_desc, uint32_t idesc,
                                         uint32_t en) {
    asm volatile(
        "{\n\t"
        ".reg .pred p;\n\t"
        "setp.ne.u32 p, %5, 0;\n\t"
        "tcgen05.mma.cta_group::1.kind::tf32 [%0], %1, %2, %3, {%4,%4,%4,%4}, p;\n\t"
        "}"
        :: "r"(d_tmem), "l"(a_desc), "l"(b_desc), "r"(idesc), "r"(0u), "r"(en)
        : "memory");
}

#define TCGEN05_ALLOC(smem_result_addr, nCols) \
    asm volatile("tcgen05.alloc.cta_group::1.sync.aligned.shared::cta.b32 [%0], %1;" \
        :: "r"((uint32_t)(smem_result_addr)), "r"((uint32_t)(nCols)) : "memory")
#define TCGEN05_RELINQUISH() \
    asm volatile("tcgen05.relinquish_alloc_permit.cta_group::1.sync.aligned;")
#define TCGEN05_DEALLOC(tmem_addr, nCols) \
    asm volatile("tcgen05.dealloc.cta_group::1.sync.aligned.b32 %0, %1;" \
        :: "r"(tmem_addr), "r"((uint32_t)(nCols)))
#define TCGEN05_COMMIT(mbar_smem_addr) \
    asm volatile("tcgen05.commit.cta_group::1.mbarrier::arrive::one.shared::cluster.b64 [%0];" \
        :: "r"((uint32_t)(mbar_smem_addr)) : "memory")
#define TCGEN05_FENCE_AFTER() \
    asm volatile("tcgen05.fence::after_thread_sync;" ::: "memory")
#define TCGEN05_WAIT_LD() \
    asm volatile("tcgen05.wait::ld.sync.aligned;" ::: "memory")
#define FENCE_ASYNC() \
    asm volatile("fence.proxy.async.shared::cta;" ::: "memory")

#define MBARRIER_INIT(mbar_smem_addr, count) \
    asm volatile("mbarrier.init.shared.b64 [%0], %1;" \
        :: "r"((uint32_t)(mbar_smem_addr)), "r"((uint32_t)(count)) : "memory")
#define MBARRIER_INVAL(mbar_smem_addr) \
    asm volatile("mbarrier.inval.shared.b64 [%0];" \
        :: "r"((uint32_t)(mbar_smem_addr)) : "memory")

#define MBARRIER_WAIT_PARITY(mbar_smem_addr, phase_parity) do { \
    uint32_t _mbar = (uint32_t)(mbar_smem_addr); \
    uint32_t _parity = (uint32_t)(phase_parity); \
    uint32_t _done; \
    asm volatile( \
        "{\n\t" \
        ".reg .pred p;\n\t" \
        "mbarrier.try_wait.parity.acquire.cta.shared::cta.b64 p, [%1], %2;\n\t" \
        "selp.b32 %0, 1, 0, p;\n\t" \
        "}" \
        : "=r"(_done) : "r"(_mbar), "r"(_parity) : "memory"); \
    if (!_done) { \
        asm volatile( \
            "{\n\t" \
            ".reg .pred P1;\n\t" \
            "WAIT_LOOP_%=:\n\t" \
            "mbarrier.try_wait.parity.acquire.cta.shared::cta.b64 P1, [%0], %1, 0x989680;\n\t" \
            "@P1 bra.uni WAIT_DONE_%=;\n\t" \
            "bra.uni WAIT_LOOP_%=;\n\t" \
            "WAIT_DONE_%=:\n\t" \
            "}" \
            :: "r"(_mbar), "r"(_parity) : "memory"); \
    } \
} while (0)

#define TCGEN05_LD_32X32B_X32(r, tmem_addr) \
    asm volatile( \
        "tcgen05.ld.sync.aligned.32x32b.x32.b32 " \
        "{%0, %1, %2, %3, %4, %5, %6, %7, " \
        " %8, %9, %10, %11, %12, %13, %14, %15, " \
        " %16, %17, %18, %19, %20, %21, %22, %23, " \
        " %24, %25, %26, %27, %28, %29, %30, %31}, [%32];" \
        : "=r"((r)[0]),  "=r"((r)[1]),  "=r"((r)[2]),  "=r"((r)[3]), \
          "=r"((r)[4]),  "=r"((r)[5]),  "=r"((r)[6]),  "=r"((r)[7]), \
          "=r"((r)[8]),  "=r"((r)[9]),  "=r"((r)[10]), "=r"((r)[11]), \
          "=r"((r)[12]), "=r"((r)[13]), "=r"((r)[14]), "=r"((r)[15]), \
          "=r"((r)[16]), "=r"((r)[17]), "=r"((r)[18]), "=r"((r)[19]), \
          "=r"((r)[20]), "=r"((r)[21]), "=r"((r)[22]), "=r"((r)[23]), \
          "=r"((r)[24]), "=r"((r)[25]), "=r"((r)[26]), "=r"((r)[27]), \
          "=r"((r)[28]), "=r"((r)[29]), "=r"((r)[30]), "=r"((r)[31]) \
        : "r"(tmem_addr))
#endif  // HAS_TC

// ---------------- kernel 0: zero out + counters ----------------
__global__ void k_zero(float* __restrict__ out) {
    size_t i = (size_t)blockIdx.x * blockDim.x + threadIdx.x;
    float4* o4 = (float4*)out;
    if (i < (size_t)T_TOK * H_DIM / 4) o4[i] = make_float4(0.f, 0.f, 0.f, 0.f);
    if (blockIdx.x == 0 && threadIdx.x < E_NUM) g_count[threadIdx.x] = 0;
}

// ---------------- kernel 1: gating (softmax top-2, routing lists) ----------------
__global__ void k_gate(const float* __restrict__ x, const float* __restrict__ gw) {
    int t = blockIdx.x;
    const float* xr = x + (size_t)t * H_DIM;
    float acc[E_NUM];
#pragma unroll
    for (int e = 0; e < E_NUM; e++) acc[e] = 0.f;
    for (int h = threadIdx.x; h < H_DIM; h += NTHREADS) {
        float xv = xr[h];
        const float* g = gw + h * E_NUM;
#pragma unroll
        for (int e = 0; e < E_NUM; e++) acc[e] += xv * g[e];
    }
#pragma unroll
    for (int e = 0; e < E_NUM; e++)
#pragma unroll
        for (int off = 16; off > 0; off >>= 1)
            acc[e] += __shfl_xor_sync(0xFFFFFFFF, acc[e], off);
    __shared__ float red[8][E_NUM];
    int wid = threadIdx.x >> 5, lid = threadIdx.x & 31;
    if (lid == 0)
#pragma unroll
        for (int e = 0; e < E_NUM; e++) red[wid][e] = acc[e];
    __syncthreads();
    if (threadIdx.x == 0) {
        float l[E_NUM];
#pragma unroll
        for (int e = 0; e < E_NUM; e++) {
            float s = 0.f;
#pragma unroll
            for (int w = 0; w < 8; w++) s += red[w][e];
            l[e] = s;
        }
        int i1 = 0;
#pragma unroll
        for (int e = 1; e < E_NUM; e++) if (l[e] > l[i1]) i1 = e;
        int i2 = (i1 == 0) ? 1 : 0;
#pragma unroll
        for (int e = 0; e < E_NUM; e++) if (e != i1 && l[e] > l[i2]) i2 = e;
        // renormalized top-2 softmax == softmax over {l1,l2}
        float e2 = expf(l[i2] - l[i1]);
        float wa = 1.f / (1.f + e2);
        float wb = 1.f - wa;
        int p1 = atomicAdd(&g_count[i1], 1);
        g_tok[i1 * T_TOK + p1] = t;  g_wt[i1 * T_TOK + p1] = wa;
        int p2 = atomicAdd(&g_count[i2], 1);
        g_tok[i2 * T_TOK + p2] = t;  g_wt[i2 * T_TOK + p2] = wb;
    }
}

// ---------------- GEMM tile geometry (tcgen05 path) ----------------
// M=128, N=256, K-chunk=32 (4 tf32 MMA steps of K=8)
#define KT 32
#define ABUF_B 16384                // 128 rows x 128B
#define BBUF_B 32768                // 256 rows x 128B

// GEMM1 smem layout
#define S1_TMEM 0
#define S1_MB   16
#define S1_TOK  64                              // 512B, ends 576 (< 1024, no overlap)
#define S1_A    1024
#define S1_B1   (S1_A + 2 * ABUF_B)             // 33792
#define S1_B3   (S1_B1 + 2 * BBUF_B)            // 99328
#define S1_END  (S1_B3 + 2 * BBUF_B)            // 164864

// ---------------- kernel 2: grouped GEMM1 (x@w1, x@w3, SwiGLU -> g_h) ----------------
__global__ void __launch_bounds__(NTHREADS, 1)
k_gemm1(const float* __restrict__ x, const float* __restrict__ w1,
        const float* __restrict__ w3) {
#if HAS_TC
    int e = blockIdx.z, nt = blockIdx.y, m = blockIdx.x;
    int cnt = g_count[e];
    if (m * 128 >= cnt) return;

    extern __shared__ char smem[];
    uint32_t sb = smem_u32(smem);
    int tid = threadIdx.x, wid = tid >> 5, lid = tid & 31;

    if (tid < 128) {
        int r = m * 128 + tid;
        ((int*)(smem + S1_TOK))[tid] = (r < cnt) ? g_tok[e * T_TOK + r] : 0;
    }
    if (wid == 0) { TCGEN05_ALLOC(sb + S1_TMEM, 512); TCGEN05_RELINQUISH(); }
    if (tid == 0) { MBARRIER_INIT(sb + S1_MB, 1); MBARRIER_INIT(sb + S1_MB + 8, 1); }
    __syncthreads();
    uint32_t tmem;
    asm volatile("ld.shared.b32 %0, [%1];" : "=r"(tmem) : "r"(sb + S1_TMEM));
    const int* stok = (const int*)(smem + S1_TOK);

    int n0 = nt * 256;
    const float* w1e = w1 + (size_t)e * H_DIM * I_DIM;
    const float* w3e = w3 + (size_t)e * H_DIM * I_DIM;

    int ph0 = 0, ph1 = 0;
    for (int kc = 0; kc < H_DIM / KT; kc++) {
        int buf = kc & 1;
        if (kc >= 2) {
            if (buf == 0) { MBARRIER_WAIT_PARITY(sb + S1_MB,     ph0); ph0 ^= 1; }
            else          { MBARRIER_WAIT_PARITY(sb + S1_MB + 8, ph1); ph1 ^= 1; }
        }
        char* sA  = smem + S1_A  + buf * ABUF_B;
        char* sB1 = smem + S1_B1 + buf * BBUF_B;
        char* sB3 = smem + S1_B3 + buf * BBUF_B;

        // A: gather 128 token rows x 32 tf32
#pragma unroll
        for (int j = 0; j < 4; j++) {
            int idx = tid + NTHREADS * j;
            int row = idx >> 3, c4 = idx & 7;
            float4 v = *(const float4*)(x + (size_t)stok[row] * H_DIM + kc * KT + c4 * 4);
            v.x = to_tf32(v.x); v.y = to_tf32(v.y); v.z = to_tf32(v.z); v.w = to_tf32(v.w);
            *(float4*)(sA + SW128(row * 128 + c4 * 16)) = v;
        }
        // B tiles: 256 n-rows x 32 k, K-major (column loads, vectorized STS)
#pragma unroll
        for (int j = 0; j < 8; j++) {
            int idx = tid + NTHREADS * j;
            int n = idx & 255, k4 = idx >> 8;
            size_t gb = (size_t)(kc * KT + k4 * 4) * I_DIM + n0 + n;
            float4 v1 = make_float4(to_tf32(w1e[gb]), to_tf32(w1e[gb + I_DIM]),
                                    to_tf32(w1e[gb + 2 * I_DIM]), to_tf32(w1e[gb + 3 * I_DIM]));
            *(float4*)(sB1 + SW128(n * 128 + k4 * 16)) = v1;
            float4 v3 = make_float4(to_tf32(w3e[gb]), to_tf32(w3e[gb + I_DIM]),
                                    to_tf32(w3e[gb + 2 * I_DIM]), to_tf32(w3e[gb + 3 * I_DIM]));
            *(float4*)(sB3 + SW128(n * 128 + k4 * 16)) = v3;
        }
        __syncthreads();
        if (wid == 0 && elect1()) {
            FENCE_ASYNC();
            uint64_t ad  = mkdesc(sb + S1_A  + buf * ABUF_B);
            uint64_t bd1 = mkdesc(sb + S1_B1 + buf * BBUF_B);
            uint64_t bd3 = mkdesc(sb + S1_B3 + buf * BBUF_B);
#pragma unroll
            for (int s = 0; s < 4; s++) {
                uint32_t en = (kc > 0 || s > 0) ? 1u : 0u;
                mma_tf32(tmem,       ad + s * 2, bd1 + s * 2, IDESC_TF32_N256, en);
                mma_tf32(tmem + 256, ad + s * 2, bd3 + s * 2, IDESC_TF32_N256, en);
            }
            TCGEN05_COMMIT(sb + S1_MB + 8 * buf);
        }
    }
    MBARRIER_WAIT_PARITY(sb + S1_MB,     ph0);
    MBARRIER_WAIT_PARITY(sb + S1_MB + 8, ph1);
    TCGEN05_FENCE_AFTER();

    // epilogue: silu(d1) * d3 -> g_h
    int row = (wid & 3) * 32 + lid;
    int grow = m * 128 + row;
    bool act = grow < cnt;
    int chalf = (wid >> 2) * 128;
    float* hrow = g_h + ((size_t)e * T_TOK + grow) * I_DIM + n0;
#pragma unroll 1
    for (int c = 0; c < 4; c++) {
        int cb = chalf + c * 32;
        uint32_t ra[32], rb[32];
        TCGEN05_LD_32X32B_X32(ra, tmem + cb);
        TCGEN05_LD_32X32B_X32(rb, tmem + 256 + cb);
        TCGEN05_WAIT_LD();
        if (act) {
#pragma unroll
            for (int q = 0; q < 32; q += 4) {
                float o[4];
#pragma unroll
                for (int u = 0; u < 4; u++) {
                    float a = __uint_as_float(ra[q + u]);
                    float b = __uint_as_float(rb[q + u]);
                    o[u] = (a / (1.0f + expf(-a))) * b;
                }
                *(float4*)(hrow + cb + q) = make_float4(o[0], o[1], o[2], o[3]);
            }
        }
    }
    __syncthreads();
    if (tid == 0) { MBARRIER_INVAL(sb + S1_MB); MBARRIER_INVAL(sb + S1_MB + 8); }
    __syncthreads();
    if (wid == 0) TCGEN05_DEALLOC(tmem, 512);
#else
    // ---------- FFMA fallback (plain sm_103 pass) ----------
    int e = blockIdx.z, nt = blockIdx.y, m = blockIdx.x;
    int cnt = g_count[e];
    if (m * 128 >= cnt) return;
    extern __shared__ char smem[];
    int*   stok = (int*)smem;
    float* As   = (float*)(smem + 512);          // 128x16
    float* B1s  = As + 128 * 16;                 // 16x132 (padded)
    float* B3s  = B1s + 16 * 132;
    int tid = threadIdx.x;
    if (tid < 128) {
        int r = m * 128 + tid;
        stok[tid] = (r < cnt) ? g_tok[e * T_TOK + r] : 0;
    }
    __syncthreads();
    int tx = tid & 15, ty = tid >> 4;
    int n0 = nt * 256;
    const float* w1e = w1 + (size_t)e * H_DIM * I_DIM;
    const float* w3e = w3 + (size_t)e * H_DIM * I_DIM;
    for (int nh = 0; nh < 2; nh++) {
        float acc1[8][8], acc3[8][8];
#pragma unroll
        for (int i = 0; i < 8; i++)
#pragma unroll
            for (int j = 0; j < 8; j++) { acc1[i][j] = 0.f; acc3[i][j] = 0.f; }
        for (int kc = 0; kc < H_DIM / 16; kc++) {
            __syncthreads();
#pragma unroll
            for (int L = 0; L < 8; L++) {
                int f = tid + 256 * L;
                int row = f >> 4, k = f & 15;
                As[f] = x[(size_t)stok[row] * H_DIM + kc * 16 + k];
            }
#pragma unroll
            for (int L = 0; L < 8; L++) {
                int f = tid + 256 * L;
                int k = f >> 7, c = f & 127;
                size_t gb = (size_t)(kc * 16 + k) * I_DIM + n0 + nh * 128 + c;
                B1s[k * 132 + c] = w1e[gb];
                B3s[k * 132 + c] = w3e[gb];
            }
            __syncthreads();
#pragma unroll
            for (int k = 0; k < 16; k++) {
                float a[8], b1[8], b3[8];
#pragma unroll
                for (int i = 0; i < 8; i++) a[i] = As[(ty * 8 + i) * 16 + k];
#pragma unroll
                for (int j = 0; j < 8; j++) {
                    b1[j] = B1s[k * 132 + tx * 8 + j];
                    b3[j] = B3s[k * 132 + tx * 8 + j];
                }
#pragma unroll
                for (int i = 0; i < 8; i++)
#pragma unroll
                    for (int j = 0; j < 8; j++) {
                        acc1[i][j] += a[i] * b1[j];
                        acc3[i][j] += a[i] * b3[j];
                    }
            }
        }
#pragma unroll
        for (int i = 0; i < 8; i++) {
            int row = ty * 8 + i, grow = m * 128 + row;
            if (grow < cnt) {
                float* hrow = g_h + ((size_t)e * T_TOK + grow) * I_DIM
                            + n0 + nh * 128 + tx * 8;
#pragma unroll
                for (int j = 0; j < 8; j++) {
                    float a = acc1[i][j];
                    hrow[j] = (a / (1.f + expf(-a))) * acc3[i][j];
                }
            }
        }
    }
#endif
}

// GEMM2 smem layout — FIXED: S2_WT ends at 1088, so A starts at 2048 (1024-aligned)
#define S2_TMEM 0
#define S2_MB   16
#define S2_TOK  64                        // 512B, ends 576
#define S2_WT   576                       // 512B, ends 1088
#define S2_A    2048
#define S2_B    (S2_A + 2 * ABUF_B)       // 34816
#define S2_END  (S2_B + 2 * BBUF_B)       // 100352

// ---------------- kernel 3: grouped GEMM2 (g_h @ w2, weighted scatter) ----------------
__global__ void __launch_bounds__(NTHREADS)
k_gemm2(const float* __restrict__ w2, float* __restrict__ out) {
#if HAS_TC
    int e = blockIdx.z, nt = blockIdx.y, m = blockIdx.x;
    int cnt = g_count[e];
    if (m * 128 >= cnt) return;

    extern __shared__ char smem[];
    uint32_t sb = smem_u32(smem);
    int tid = threadIdx.x, wid = tid >> 5, lid = tid & 31;

    if (tid < 128) {
        int r = m * 128 + tid;
        bool a = r < cnt;
        ((int*)(smem + S2_TOK))[tid]   = a ? g_tok[e * T_TOK + r] : 0;
        ((float*)(smem + S2_WT))[tid]  = a ? g_wt[e * T_TOK + r] : 0.f;
    }
    // 256 TMEM cols only (D is 128x256) -> two CTAs/SM can hold TMEM at once
    if (wid == 0) { TCGEN05_ALLOC(sb + S2_TMEM, 256); TCGEN05_RELINQUISH(); }
    if (tid == 0) { MBARRIER_INIT(sb + S2_MB, 1); MBARRIER_INIT(sb + S2_MB + 8, 1); }
    __syncthreads();
    uint32_t tmem;
    asm volatile("ld.shared.b32 %0, [%1];" : "=r"(tmem) : "r"(sb + S2_TMEM));

    int n0 = nt * 256;
    const float* w2e = w2 + (size_t)e * I_DIM * H_DIM;
    const float* hbase = g_h + ((size_t)e * T_TOK + (size_t)m * 128) * I_DIM;

    int ph0 = 0, ph1 = 0;
    for (int kc = 0; kc < I_DIM / KT; kc++) {
        int buf = kc & 1;
        if (kc >= 2) {
            if (buf == 0) { MBARRIER_WAIT_PARITY(sb + S2_MB,     ph0); ph0 ^= 1; }
            else          { MBARRIER_WAIT_PARITY(sb + S2_MB + 8, ph1); ph1 ^= 1; }
        }
        char* sA = smem + S2_A + buf * ABUF_B;
        char* sB = smem + S2_B + buf * BBUF_B;
#pragma unroll
        for (int j = 0; j < 4; j++) {
            int idx = tid + NTHREADS * j;
            int row = idx >> 3, c4 = idx & 7;
            float4 v = *(const float4*)(hbase + (size_t)row * I_DIM + kc * KT + c4 * 4);
            v.x = to_tf32(v.x); v.y = to_tf32(v.y); v.z = to_tf32(v.z); v.w = to_tf32(v.w);
            *(float4*)(sA + SW128(row * 128 + c4 * 16)) = v;
        }
#pragma unroll
        for (int j = 0; j < 8; j++) {
            int idx = tid + NTHREADS * j;
            int n = idx & 255, k4 = idx >> 8;
            size_t gb = (size_t)(kc * KT + k4 * 4) * H_DIM + n0 + n;
            float4 v = make_float4(to_tf32(w2e[gb]), to_tf32(w2e[gb + H_DIM]),
                                   to_tf32(w2e[gb + 2 * H_DIM]), to_tf32(w2e[gb + 3 * H_DIM]));
            *(float4*)(sB + SW128(n * 128 + k4 * 16)) = v;
        }
        __syncthreads();
        if (wid == 0 && elect1()) {
            FENCE_ASYNC();
            uint64_t ad = mkdesc(sb + S2_A + buf * ABUF_B);
            uint64_t bd = mkdesc(sb + S2_B + buf * BBUF_B);
#pragma unroll
            for (int s = 0; s < 4; s++) {
                uint32_t en = (kc > 0 || s > 0) ? 1u : 0u;
                mma_tf32(tmem, ad + s * 2, bd + s * 2, IDESC_TF32_N256, en);
            }
            TCGEN05_COMMIT(sb + S2_MB + 8 * buf);
        }
    }
    MBARRIER_WAIT_PARITY(sb + S2_MB,     ph0);
    MBARRIER_WAIT_PARITY(sb + S2_MB + 8, ph1);
    TCGEN05_FENCE_AFTER();

    int row = (wid & 3) * 32 + lid;
    int grow = m * 128 + row;
    bool act = grow < cnt;
    int tok = ((const int*)(smem + S2_TOK))[row];
    float wt = ((const float*)(smem + S2_WT))[row];
    int chalf = (wid >> 2) * 128;
    float* orow = out + (size_t)tok * H_DIM + n0;
#pragma unroll 1
    for (int c = 0; c < 4; c++) {
        int cb = chalf + c * 32;
        uint32_t r[32];
        TCGEN05_LD_32X32B_X32(r, tmem + cb);
        TCGEN05_WAIT_LD();
        if (act) {
#pragma unroll
            for (int q = 0; q < 32; q++)
                atomicAdd(&orow[cb + q], wt * __uint_as_float(r[q]));
        }
    }
    __syncthreads();
    if (tid == 0) { MBARRIER_INVAL(sb + S2_MB); MBARRIER_INVAL(sb + S2_MB + 8); }
    __syncthreads();
    if (wid == 0) TCGEN05_DEALLOC(tmem, 256);
#else
    // ---------- FFMA fallback (plain sm_103 pass) ----------
    int e = blockIdx.z, nt = blockIdx.y, m = blockIdx.x;
    int cnt = g_count[e];
    if (m * 128 >= cnt) return;
    extern __shared__ char smem[];
    int*   stok = (int*)smem;
    float* swt  = (float*)(smem + 512);
    float* As   = (float*)(smem + 1024);         // 128x16
    float* Bs   = As + 128 * 16;                 // 16x132 (padded)
    int tid = threadIdx.x;
    if (tid < 128) {
        int r = m * 128 + tid;
        bool a = r < cnt;
        stok[tid] = a ? g_tok[e * T_TOK + r] : 0;
        swt[tid]  = a ? g_wt[e * T_TOK + r] : 0.f;
    }
    __syncthreads();
    int tx = tid & 15, ty = tid >> 4;
    int n0 = nt * 256;
    const float* w2e = w2 + (size_t)e * I_DIM * H_DIM;
    const float* hbase = g_h + ((size_t)e * T_TOK + (size_t)m * 128) * I_DIM;
    for (int nh = 0; nh < 2; nh++) {
        float acc[8][8];
#pragma unroll
        for (int i = 0; i < 8; i++)
#pragma unroll
            for (int j = 0; j < 8; j++) acc[i][j] = 0.f;
        for (int kc = 0; kc < I_DIM / 16; kc++) {
            __syncthreads();
#pragma unroll
            for (int L = 0; L < 8; L++) {
                int f = tid + 256 * L;
                int row = f >> 4, k = f & 15;
                As[f] = hbase[(size_t)row * I_DIM + kc * 16 + k];
            }
#pragma unroll
            for (int L = 0; L < 8; L++) {
                int f = tid + 256 * L;
                int k = f >> 7, c = f & 127;
                Bs[k * 132 + c] = w2e[(size_t)(kc * 16 + k) * H_DIM + n0 + nh * 128 + c];
            }
            __syncthreads();
#pragma unroll
            for (int k = 0; k < 16; k++) {
                float a[8], b[8];
#pragma unroll
                for (int i = 0; i < 8; i++) a[i] = As[(ty * 8 + i) * 16 + k];
#pragma unroll
                for (int j = 0; j < 8; j++) b[j] = Bs[k * 132 + tx * 8 + j];
#pragma unroll
                for (int i = 0; i < 8; i++)
#pragma unroll
                    for (int j = 0; j < 8; j++) acc[i][j] += a[i] * b[j];
            }
        }
#pragma unroll
        for (int i = 0; i < 8; i++) {
            int row = ty * 8 + i, grow = m * 128 + row;
            if (grow < cnt) {
                float wt = swt[row];
                float* orow = out + (size_t)stok[row] * H_DIM + n0 + nh * 128 + tx * 8;
#pragma unroll
                for (int j = 0; j < 8; j++)
                    atomicAdd(&orow[j], wt * acc[i][j]);
            }
        }
    }
#endif
}

// ---------------- launch ----------------
extern "C" void kernel_launch(void* const* d_in, const int* in_sizes, int n_in,
                              void* d_out, int out_size) {
    const float* x  = (const float*)d_in[0];   // hidden_states [T,H]
    const float* gw = (const float*)d_in[1];   // gate_w [H,E]
    const float* w1 = (const float*)d_in[2];   // [E,H,I]
    const float* w3 = (const float*)d_in[3];   // [E,H,I]
    const float* w2 = (const float*)d_in[4];   // [E,I,H]
    float* out = (float*)d_out;

    cudaFuncSetAttribute(k_gemm1, cudaFuncAttributeMaxDynamicSharedMemorySize, S1_END);
    cudaFuncSetAttribute(k_gemm2, cudaFuncAttributeMaxDynamicSharedMemorySize, S2_END);

    k_zero<<<(T_TOK * H_DIM / 4 + NTHREADS - 1) / NTHREADS, NTHREADS>>>(out);
    k_gate<<<T_TOK, NTHREADS>>>(x, gw);
    // grid.x = m-slot (fastest -> co-resident CTAs share (e,n) B stream in L2)
    k_gemm1<<<dim3(T_TOK / 128, I_DIM / 256, E_NUM), NTHREADS, S1_END>>>(x, w1, w3);
    k_gemm2<<<dim3(T_TOK / 128, H_DIM / 256, E_NUM), NTHREADS, S2_END>>>(w2, out);
}

// round 4
// speedup vs baseline: 1.5825x; 1.5825x over previous
#include <cuda_runtime.h>
#include <cstdint>

// ---------------- problem constants ----------------
#define T_TOK 8192          // B*S
#define H_DIM 1024
#define E_NUM 8
#define I_DIM 4096
#define NT 512              // threads per GEMM CTA

// tcgen05 only legal in the sm_103a arch-accelerated pass
#if !defined(__CUDA_ARCH__) || defined(__CUDA_ARCH_FEAT_SM103_ALL)
#define HAS_TC 1
#else
#define HAS_TC 0
#endif

// ---------------- device scratch (static, allocation-free) ----------------
__device__ int   g_count[E_NUM];
__device__ int   g_tok[E_NUM * T_TOK];
__device__ float g_wt [E_NUM * T_TOK];
__device__ float g_h  [268435456];                       // [E*T, I]  1.07GB
__device__ float g_xa [(size_t)E_NUM * T_TOK * H_DIM];   // gathered+rounded x, 256MB
__device__ float g_w1t[(size_t)E_NUM * I_DIM * H_DIM];   // [E][I][H] rounded, 134MB
__device__ float g_w3t[(size_t)E_NUM * I_DIM * H_DIM];
__device__ float g_w2t[(size_t)E_NUM * H_DIM * I_DIM];   // [E][H][I] rounded

// ---------------- common helpers ----------------
__device__ __forceinline__ float to_tf32(float f) {
    uint32_t u;
    asm("cvt.rna.tf32.f32 %0, %1;" : "=r"(u) : "f"(f));
    return __uint_as_float(u);
}
#define SW128(x) ((x) ^ (((x) >> 3) & 0x70))

#if HAS_TC
__device__ __forceinline__ uint32_t smem_u32(const void* p) {
    uint32_t a;
    asm("{ .reg .u64 t; cvta.to.shared.u64 t, %1; cvt.u32.u64 %0, t; }"
        : "=r"(a) : "l"(p));
    return a;
}
__device__ __forceinline__ uint32_t elect1() {
    uint32_t p;
    asm volatile("{ .reg .pred p; elect.sync _|p, 0xFFFFFFFF; selp.b32 %0,1,0,p; }" : "=r"(p));
    return p;
}
__device__ __forceinline__ void cpa16(uint32_t dst, const float* src) {
    asm volatile("cp.async.cg.shared.global [%0], [%1], 16;" :: "r"(dst), "l"(src));
}
#define CP_COMMIT() asm volatile("cp.async.commit_group;" ::: "memory")
#define CP_WAIT1()  asm volatile("cp.async.wait_group 1;" ::: "memory")
#define CP_WAIT0()  asm volatile("cp.async.wait_group 0;" ::: "memory")

// SW128 K-major smem descriptor (Blackwell): layout=2, version=1, SBO=64, LBO=1
static constexpr uint64_t DESC_BASE =
    (2ull << 61) | (1ull << 46) | (64ull << 32) | (1ull << 16);
__device__ __forceinline__ uint64_t mkdesc(uint32_t smem_addr) {
    return DESC_BASE | ((uint64_t)(smem_addr >> 4) & 0x3FFF);
}
// idesc: D=F32(1<<4), A=TF32(2<<7), B=TF32(2<<10), N=256 (32<<17), M=128 (8<<24)
static constexpr uint32_t IDESC_TF32_N256 =
    (1u << 4) | (2u << 7) | (2u << 10) | (32u << 17) | (8u << 24);

__device__ __forceinline__ void mma_tf32(uint32_t d_tmem, uint64_t a_desc,
                                         uint64_t b_desc, uint32_t en) {
    asm volatile(
        "{\n\t"
        ".reg .pred p;\n\t"
        "setp.ne.u32 p, %4, 0;\n\t"
        "tcgen05.mma.cta_group::1.kind::tf32 [%0], %1, %2, %3, {%5,%5,%5,%5}, p;\n\t"
        "}"
        :: "r"(d_tmem), "l"(a_desc), "l"(b_desc), "r"(IDESC_TF32_N256),
           "r"(en), "r"(0u)
        : "memory");
}

#define TCGEN05_ALLOC(smem_result_addr, nCols) \
    asm volatile("tcgen05.alloc.cta_group::1.sync.aligned.shared::cta.b32 [%0], %1;" \
        :: "r"((uint32_t)(smem_result_addr)), "r"((uint32_t)(nCols)) : "memory")
#define TCGEN05_RELINQUISH() \
    asm volatile("tcgen05.relinquish_alloc_permit.cta_group::1.sync.aligned;")
#define TCGEN05_DEALLOC(tmem_addr, nCols) \
    asm volatile("tcgen05.dealloc.cta_group::1.sync.aligned.b32 %0, %1;" \
        :: "r"(tmem_addr), "r"((uint32_t)(nCols)))
#define TCGEN05_COMMIT(mbar_smem_addr) \
    asm volatile("tcgen05.commit.cta_group::1.mbarrier::arrive::one.shared::cluster.b64 [%0];" \
        :: "r"((uint32_t)(mbar_smem_addr)) : "memory")
#define TCGEN05_FENCE_AFTER() \
    asm volatile("tcgen05.fence::after_thread_sync;" ::: "memory")
#define TCGEN05_WAIT_LD() \
    asm volatile("tcgen05.wait::ld.sync.aligned;" ::: "memory")
#define FENCE_ASYNC() \
    asm volatile("fence.proxy.async.shared::cta;" ::: "memory")

#define MBARRIER_INIT(mbar_smem_addr, count) \
    asm volatile("mbarrier.init.shared.b64 [%0], %1;" \
        :: "r"((uint32_t)(mbar_smem_addr)), "r"((uint32_t)(count)) : "memory")
#define MBARRIER_INVAL(mbar_smem_addr) \
    asm volatile("mbarrier.inval.shared.b64 [%0];" \
        :: "r"((uint32_t)(mbar_smem_addr)) : "memory")

#define MBARRIER_WAIT_PARITY(mbar_smem_addr, phase_parity) do { \
    uint32_t _mbar = (uint32_t)(mbar_smem_addr); \
    uint32_t _parity = (uint32_t)(phase_parity); \
    uint32_t _done; \
    asm volatile( \
        "{\n\t" \
        ".reg .pred p;\n\t" \
        "mbarrier.try_wait.parity.acquire.cta.shared::cta.b64 p, [%1], %2;\n\t" \
        "selp.b32 %0, 1, 0, p;\n\t" \
        "}" \
        : "=r"(_done) : "r"(_mbar), "r"(_parity) : "memory"); \
    if (!_done) { \
        asm volatile( \
            "{\n\t" \
            ".reg .pred P1;\n\t" \
            "WAIT_LOOP_%=:\n\t" \
            "mbarrier.try_wait.parity.acquire.cta.shared::cta.b64 P1, [%0], %1, 0x989680;\n\t" \
            "@P1 bra.uni WAIT_DONE_%=;\n\t" \
            "bra.uni WAIT_LOOP_%=;\n\t" \
            "WAIT_DONE_%=:\n\t" \
            "}" \
            :: "r"(_mbar), "r"(_parity) : "memory"); \
    } \
} while (0)

#define TCGEN05_LD_32X32B_X32(r, tmem_addr) \
    asm volatile( \
        "tcgen05.ld.sync.aligned.32x32b.x32.b32 " \
        "{%0, %1, %2, %3, %4, %5, %6, %7, " \
        " %8, %9, %10, %11, %12, %13, %14, %15, " \
        " %16, %17, %18, %19, %20, %21, %22, %23, " \
        " %24, %25, %26, %27, %28, %29, %30, %31}, [%32];" \
        : "=r"((r)[0]),  "=r"((r)[1]),  "=r"((r)[2]),  "=r"((r)[3]), \
          "=r"((r)[4]),  "=r"((r)[5]),  "=r"((r)[6]),  "=r"((r)[7]), \
          "=r"((r)[8]),  "=r"((r)[9]),  "=r"((r)[10]), "=r"((r)[11]), \
          "=r"((r)[12]), "=r"((r)[13]), "=r"((r)[14]), "=r"((r)[15]), \
          "=r"((r)[16]), "=r"((r)[17]), "=r"((r)[18]), "=r"((r)[19]), \
          "=r"((r)[20]), "=r"((r)[21]), "=r"((r)[22]), "=r"((r)[23]), \
          "=r"((r)[24]), "=r"((r)[25]), "=r"((r)[26]), "=r"((r)[27]), \
          "=r"((r)[28]), "=r"((r)[29]), "=r"((r)[30]), "=r"((r)[31]) \
        : "r"(tmem_addr))
#endif  // HAS_TC

// ---------------- kernel 0: zero out + counters ----------------
__global__ void k_zero(float* __restrict__ out) {
    size_t i = (size_t)blockIdx.x * blockDim.x + threadIdx.x;
    float4* o4 = (float4*)out;
    if (i < (size_t)T_TOK * H_DIM / 4) o4[i] = make_float4(0.f, 0.f, 0.f, 0.f);
    if (blockIdx.x == 0 && threadIdx.x < E_NUM) g_count[threadIdx.x] = 0;
}

// ---------------- kernel 1: gating (softmax top-2, routing lists) ----------------
__global__ void k_gate(const float* __restrict__ x, const float* __restrict__ gw) {
    int t = blockIdx.x;
    const float* xr = x + (size_t)t * H_DIM;
    float acc[E_NUM];
#pragma unroll
    for (int e = 0; e < E_NUM; e++) acc[e] = 0.f;
    for (int h = threadIdx.x; h < H_DIM; h += 256) {
        float xv = xr[h];
        const float* g = gw + h * E_NUM;
#pragma unroll
        for (int e = 0; e < E_NUM; e++) acc[e] += xv * g[e];
    }
#pragma unroll
    for (int e = 0; e < E_NUM; e++)
#pragma unroll
        for (int off = 16; off > 0; off >>= 1)
            acc[e] += __shfl_xor_sync(0xFFFFFFFF, acc[e], off);
    __shared__ float red[8][E_NUM];
    int wid = threadIdx.x >> 5, lid = threadIdx.x & 31;
    if (lid == 0)
#pragma unroll
        for (int e = 0; e < E_NUM; e++) red[wid][e] = acc[e];
    __syncthreads();
    if (threadIdx.x == 0) {
        float l[E_NUM];
#pragma unroll
        for (int e = 0; e < E_NUM; e++) {
            float s = 0.f;
#pragma unroll
            for (int w = 0; w < 8; w++) s += red[w][e];
            l[e] = s;
        }
        int i1 = 0;
#pragma unroll
        for (int e = 1; e < E_NUM; e++) if (l[e] > l[i1]) i1 = e;
        int i2 = (i1 == 0) ? 1 : 0;
#pragma unroll
        for (int e = 0; e < E_NUM; e++) if (e != i1 && l[e] > l[i2]) i2 = e;
        float e2 = expf(l[i2] - l[i1]);
        float wa = 1.f / (1.f + e2);
        float wb = 1.f - wa;
        int p1 = atomicAdd(&g_count[i1], 1);
        g_tok[i1 * T_TOK + p1] = t;  g_wt[i1 * T_TOK + p1] = wa;
        int p2 = atomicAdd(&g_count[i2], 1);
        g_tok[i2 * T_TOK + p2] = t;  g_wt[i2 * T_TOK + p2] = wb;
    }
}

// ---------------- prep: transpose + tf32-round weights ----------------
// w1/w3 [E][H][I] -> g_w1t/g_w3t [E][I][H]
__global__ void k_tr13(const float* __restrict__ w1, const float* __restrict__ w3) {
    __shared__ float tile[32][33];
    int e = blockIdx.z & 7;
    const float* src = (blockIdx.z < E_NUM ? w1 : w3) + (size_t)e * H_DIM * I_DIM;
    float* dst = (blockIdx.z < E_NUM ? g_w1t : g_w3t) + (size_t)e * I_DIM * H_DIM;
    int i0 = blockIdx.x * 32, h0 = blockIdx.y * 32;
    int tx = threadIdx.x & 31, ty = threadIdx.x >> 5;   // 256 thr
#pragma unroll
    for (int r = 0; r < 32; r += 8)
        tile[ty + r][tx] = to_tf32(src[(size_t)(h0 + ty + r) * I_DIM + i0 + tx]);
    __syncthreads();
#pragma unroll
    for (int r = 0; r < 32; r += 8)
        dst[(size_t)(i0 + ty + r) * H_DIM + h0 + tx] = tile[tx][ty + r];
}
// w2 [E][I][H] -> g_w2t [E][H][I]
__global__ void k_tr2(const float* __restrict__ w2) {
    __shared__ float tile[32][33];
    int e = blockIdx.z;
    const float* src = w2 + (size_t)e * I_DIM * H_DIM;
    float* dst = g_w2t + (size_t)e * H_DIM * I_DIM;
    int h0 = blockIdx.x * 32, i0 = blockIdx.y * 32;
    int tx = threadIdx.x & 31, ty = threadIdx.x >> 5;
#pragma unroll
    for (int r = 0; r < 32; r += 8)
        tile[ty + r][tx] = to_tf32(src[(size_t)(i0 + ty + r) * H_DIM + h0 + tx]);
    __syncthreads();
#pragma unroll
    for (int r = 0; r < 32; r += 8)
        dst[(size_t)(h0 + ty + r) * I_DIM + i0 + tx] = tile[tx][ty + r];
}

// ---------------- pack: gather + round x rows per expert slot ----------------
__global__ void k_pack(const float* __restrict__ x) {
    int e = blockIdx.y;
    int cnt = g_count[e];
    int slot = blockIdx.x * 8 + (threadIdx.x >> 5);
    int c = threadIdx.x & 31;
    if (slot >= cnt) return;
    int tok = g_tok[e * T_TOK + slot];
    const float4* src = (const float4*)(x + (size_t)tok * H_DIM);
    float4* dst = (float4*)(g_xa + ((size_t)e * T_TOK + slot) * H_DIM);
#pragma unroll
    for (int j = 0; j < 8; j++) {
        float4 v = src[c + 32 * j];
        v.x = to_tf32(v.x); v.y = to_tf32(v.y); v.z = to_tf32(v.z); v.w = to_tf32(v.w);
        dst[c + 32 * j] = v;
    }
}

// ---------------- GEMM geometry ----------------
// K-chunk = 32 (4 tf32 K=8 MMA steps); 2-stage cp.async pipeline
#define S_MB    16
#define S1_BUF  1024
#define STG1    81920                 // A 16K + B1 32K + B3 32K
#define S1_SMEM (S1_BUF + 2 * STG1)  // 164864
#define S2_TOKS 64
#define S2_WTS  576
#define S2_BUF  2048
#define STG2    81920                 // A 16K + B 64K
#define S2_SMEM (S2_BUF + 2 * STG2)  // 165888

// ---------------- kernel: grouped GEMM1 (xa@w1t, xa@w3t, SwiGLU -> g_h) ------
// M=128 slots, N=256 I-cols (dual accumulator d1/d3 = 512 TMEM cols)
__global__ void __launch_bounds__(NT, 1)
k_gemm1() {
#if HAS_TC
    int e = blockIdx.z, nt = blockIdx.y, m = blockIdx.x;
    int cnt = g_count[e];
    if (m * 128 >= cnt) return;

    extern __shared__ char smem[];
    uint32_t sb = smem_u32(smem);
    int tid = threadIdx.x, wid = tid >> 5, lid = tid & 31;

    if (wid == 0) { TCGEN05_ALLOC(sb, 512); TCGEN05_RELINQUISH(); }
    if (tid == 0) { MBARRIER_INIT(sb + S_MB, 1); MBARRIER_INIT(sb + S_MB + 8, 1); }
    __syncthreads();
    uint32_t tmem;
    asm volatile("ld.shared.b32 %0, [%1];" : "=r"(tmem) : "r"(sb));

    int n0 = nt * 256;
    const float* Ab  = g_xa  + ((size_t)e * T_TOK + (size_t)m * 128) * H_DIM;
    const float* B1b = g_w1t + ((size_t)e * I_DIM + n0) * H_DIM;
    const float* B3b = g_w3t + ((size_t)e * I_DIM + n0) * H_DIM;

    auto issue = [&](int st, int kc) {
        uint32_t sA  = sb + S1_BUF + st * STG1;
        uint32_t sB1 = sA + 16384;
        uint32_t sB3 = sB1 + 32768;
        int ko = kc * 32;
#pragma unroll
        for (int j = 0; j < 2; j++) {                 // A: 1024 16B chunks
            int idx = tid + NT * j;
            int row = idx >> 3, c4 = idx & 7;
            cpa16(sA + SW128(row * 128 + c4 * 16), Ab + (size_t)row * H_DIM + ko + c4 * 4);
        }
#pragma unroll
        for (int j = 0; j < 4; j++) {                 // B1,B3: 2048 chunks each
            int idx = tid + NT * j;
            int n = idx >> 3, c4 = idx & 7;
            cpa16(sB1 + SW128(n * 128 + c4 * 16), B1b + (size_t)n * H_DIM + ko + c4 * 4);
            cpa16(sB3 + SW128(n * 128 + c4 * 16), B3b + (size_t)n * H_DIM + ko + c4 * 4);
        }
        CP_COMMIT();
    };

    issue(0, 0);
    issue(1, 1);

    const int NK = H_DIM / 32;  // 32
    int ph0 = 0, ph1 = 0;
    for (int kc = 0; kc < NK; kc++) {
        int st = kc & 1;
        if (kc + 2 < NK) CP_WAIT1(); else CP_WAIT0();
        __syncthreads();
        if (wid == 0 && elect1()) {
            FENCE_ASYNC();
            uint32_t base = sb + S1_BUF + st * STG1;
            uint64_t ad  = mkdesc(base);
            uint64_t bd1 = mkdesc(base + 16384);
            uint64_t bd3 = mkdesc(base + 49152);
#pragma unroll
            for (int s = 0; s < 4; s++) {
                uint32_t en = (kc > 0 || s > 0) ? 1u : 0u;
                mma_tf32(tmem,       ad + s * 2, bd1 + s * 2, en);
                mma_tf32(tmem + 256, ad + s * 2, bd3 + s * 2, en);
            }
            TCGEN05_COMMIT(sb + S_MB + 8 * st);
        }
        if (kc + 2 < NK) {
            if (st == 0) { MBARRIER_WAIT_PARITY(sb + S_MB,     ph0); ph0 ^= 1; }
            else         { MBARRIER_WAIT_PARITY(sb + S_MB + 8, ph1); ph1 ^= 1; }
            issue(st, kc + 2);
        }
    }
    MBARRIER_WAIT_PARITY(sb + S_MB,     ph0);
    MBARRIER_WAIT_PARITY(sb + S_MB + 8, ph1);
    TCGEN05_FENCE_AFTER();

    // epilogue: silu(d1)*d3, round tf32, -> g_h
    int row = (wid & 3) * 32 + lid;
    int grow = m * 128 + row;
    bool act = grow < cnt;
    int c0 = (wid >> 2) * 64;                          // 4 warpgroups x 64 cols
    float* hrow = g_h + ((size_t)e * T_TOK + (size_t)m * 128 + row) * I_DIM + n0;
#pragma unroll 1
    for (int cb = 0; cb < 64; cb += 32) {
        uint32_t ra[32], rb[32];
        TCGEN05_LD_32X32B_X32(ra, tmem + c0 + cb);
        TCGEN05_LD_32X32B_X32(rb, tmem + 256 + c0 + cb);
        TCGEN05_WAIT_LD();
        if (act) {
#pragma unroll
            for (int q = 0; q < 32; q += 4) {
                float o[4];
#pragma unroll
                for (int u = 0; u < 4; u++) {
                    float a = __uint_as_float(ra[q + u]);
                    float b = __uint_as_float(rb[q + u]);
                    o[u] = to_tf32((a / (1.0f + expf(-a))) * b);
                }
                *(float4*)(hrow + c0 + cb + q) = make_float4(o[0], o[1], o[2], o[3]);
            }
        }
    }
    __syncthreads();
    if (tid == 0) { MBARRIER_INVAL(sb + S_MB); MBARRIER_INVAL(sb + S_MB + 8); }
    __syncthreads();
    if (wid == 0) TCGEN05_DEALLOC(tmem, 512);
#else
    // ---------- FFMA fallback ----------
    int e = blockIdx.z, nt = blockIdx.y, m = blockIdx.x;
    int cnt = g_count[e];
    if (m * 128 >= cnt) return;
    extern __shared__ char smem[];
    float* As  = (float*)smem;            // 128x16
    float* B1s = As + 2048;               // 16x132
    float* B3s = B1s + 16 * 132;
    int tid = threadIdx.x;
    int tx = tid & 15, ty = tid >> 4;     // ty 0..31
    int n0 = nt * 256;
    const float* Ab = g_xa + ((size_t)e * T_TOK + (size_t)m * 128) * H_DIM;
    for (int nh = 0; nh < 2; nh++) {
        float a1[4][8], a3[4][8];
#pragma unroll
        for (int i = 0; i < 4; i++)
#pragma unroll
            for (int j = 0; j < 8; j++) { a1[i][j] = 0.f; a3[i][j] = 0.f; }
        for (int kc = 0; kc < H_DIM / 16; kc++) {
            __syncthreads();
#pragma unroll
            for (int L = 0; L < 4; L++) {
                int f = tid + NT * L;
                int row = f >> 4, k = f & 15;
                As[f] = Ab[(size_t)row * H_DIM + kc * 16 + k];
            }
#pragma unroll
            for (int L = 0; L < 4; L++) {
                int f = tid + NT * L;
                int k = f >> 7, c = f & 127;
                B1s[k * 132 + c] = g_w1t[((size_t)e * I_DIM + n0 + nh * 128 + c) * H_DIM + kc * 16 + k];
                B3s[k * 132 + c] = g_w3t[((size_t)e * I_DIM + n0 + nh * 128 + c) * H_DIM + kc * 16 + k];
            }
            __syncthreads();
#pragma unroll
            for (int k = 0; k < 16; k++) {
                float av[4], b1[8], b3[8];
#pragma unroll
                for (int i = 0; i < 4; i++) av[i] = As[(ty * 4 + i) * 16 + k];
#pragma unroll
                for (int j = 0; j < 8; j++) {
                    b1[j] = B1s[k * 132 + tx * 8 + j];
                    b3[j] = B3s[k * 132 + tx * 8 + j];
                }
#pragma unroll
                for (int i = 0; i < 4; i++)
#pragma unroll
                    for (int j = 0; j < 8; j++) {
                        a1[i][j] += av[i] * b1[j];
                        a3[i][j] += av[i] * b3[j];
                    }
            }
        }
#pragma unroll
        for (int i = 0; i < 4; i++) {
            int row = ty * 4 + i, grow = m * 128 + row;
            if (grow < cnt) {
                float* hrow = g_h + ((size_t)e * T_TOK + grow) * I_DIM + n0 + nh * 128 + tx * 8;
#pragma unroll
                for (int j = 0; j < 8; j++) {
                    float a = a1[i][j];
                    hrow[j] = to_tf32((a / (1.f + expf(-a))) * a3[i][j]);
                }
            }
        }
    }
#endif
}

// ---------------- kernel: grouped GEMM2 (g_h @ w2t, weighted scatter) --------
// M=128, N=512 (dual accumulator = 512 TMEM cols)
__global__ void __launch_bounds__(NT, 1)
k_gemm2(float* __restrict__ out) {
#if HAS_TC
    int e = blockIdx.z, nt = blockIdx.y, m = blockIdx.x;
    int cnt = g_count[e];
    if (m * 128 >= cnt) return;

    extern __shared__ char smem[];
    uint32_t sb = smem_u32(smem);
    int tid = threadIdx.x, wid = tid >> 5, lid = tid & 31;

    if (tid < 128) {
        int r = m * 128 + tid;
        bool a = r < cnt;
        ((int*)(smem + S2_TOKS))[tid]  = a ? g_tok[e * T_TOK + r] : 0;
        ((float*)(smem + S2_WTS))[tid] = a ? g_wt[e * T_TOK + r] : 0.f;
    }
    if (wid == 0) { TCGEN05_ALLOC(sb, 512); TCGEN05_RELINQUISH(); }
    if (tid == 0) { MBARRIER_INIT(sb + S_MB, 1); MBARRIER_INIT(sb + S_MB + 8, 1); }
    __syncthreads();
    uint32_t tmem;
    asm volatile("ld.shared.b32 %0, [%1];" : "=r"(tmem) : "r"(sb));

    int n0 = nt * 512;
    const float* Ab = g_h   + ((size_t)e * T_TOK + (size_t)m * 128) * I_DIM;
    const float* Bb = g_w2t + ((size_t)e * H_DIM + n0) * I_DIM;

    auto issue = [&](int st, int kc) {
        uint32_t sA = sb + S2_BUF + st * STG2;
        uint32_t sB = sA + 16384;
        int ko = kc * 32;
#pragma unroll
        for (int j = 0; j < 2; j++) {                 // A: 1024 chunks
            int idx = tid + NT * j;
            int row = idx >> 3, c4 = idx & 7;
            cpa16(sA + SW128(row * 128 + c4 * 16), Ab + (size_t)row * I_DIM + ko + c4 * 4);
        }
#pragma unroll
        for (int j = 0; j < 8; j++) {                 // B: 512 rows = 4096 chunks
            int idx = tid + NT * j;
            int n = idx >> 3, c4 = idx & 7;
            cpa16(sB + SW128(n * 128 + c4 * 16), Bb + (size_t)n * I_DIM + ko + c4 * 4);
        }
        CP_COMMIT();
    };

    issue(0, 0);
    issue(1, 1);

    const int NK = I_DIM / 32;  // 128
    int ph0 = 0, ph1 = 0;
    for (int kc = 0; kc < NK; kc++) {
        int st = kc & 1;
        if (kc + 2 < NK) CP_WAIT1(); else CP_WAIT0();
        __syncthreads();
        if (wid == 0 && elect1()) {
            FENCE_ASYNC();
            uint32_t base = sb + S2_BUF + st * STG2;
            uint64_t ad    = mkdesc(base);
            uint64_t bd_lo = mkdesc(base + 16384);
            uint64_t bd_hi = mkdesc(base + 16384 + 32768);
#pragma unroll
            for (int s = 0; s < 4; s++) {
                uint32_t en = (kc > 0 || s > 0) ? 1u : 0u;
                mma_tf32(tmem,       ad + s * 2, bd_lo + s * 2, en);
                mma_tf32(tmem + 256, ad + s * 2, bd_hi + s * 2, en);
            }
            TCGEN05_COMMIT(sb + S_MB + 8 * st);
        }
        if (kc + 2 < NK) {
            if (st == 0) { MBARRIER_WAIT_PARITY(sb + S_MB,     ph0); ph0 ^= 1; }
            else         { MBARRIER_WAIT_PARITY(sb + S_MB + 8, ph1); ph1 ^= 1; }
            issue(st, kc + 2);
        }
    }
    MBARRIER_WAIT_PARITY(sb + S_MB,     ph0);
    MBARRIER_WAIT_PARITY(sb + S_MB + 8, ph1);
    TCGEN05_FENCE_AFTER();

    // epilogue: weighted atomic scatter; 512 cols via 4 warpgroups x 128 cols
    int row = (wid & 3) * 32 + lid;
    int grow = m * 128 + row;
    bool act = grow < cnt;
    int tok = ((const int*)(smem + S2_TOKS))[row];
    float wt = ((const float*)(smem + S2_WTS))[row];
    int c0 = (wid >> 2) * 128;
    float* orow = out + (size_t)tok * H_DIM + n0;
#pragma unroll 1
    for (int cb = 0; cb < 128; cb += 32) {
        uint32_t r[32];
        // accumulator 0 covers cols 0..255 (tmem..+255), acc 1 covers 256..511
        uint32_t taddr = (c0 + cb < 256) ? (tmem + c0 + cb) : (tmem + 256 + (c0 + cb - 256));
        TCGEN05_LD_32X32B_X32(r, taddr);
        TCGEN05_WAIT_LD();
        if (act) {
#pragma unroll
            for (int q = 0; q < 32; q++)
                atomicAdd(&orow[c0 + cb + q], wt * __uint_as_float(r[q]));
        }
    }
    __syncthreads();
    if (tid == 0) { MBARRIER_INVAL(sb + S_MB); MBARRIER_INVAL(sb + S_MB + 8); }
    __syncthreads();
    if (wid == 0) TCGEN05_DEALLOC(tmem, 512);
#else
    // ---------- FFMA fallback ----------
    int e = blockIdx.z, nt = blockIdx.y, m = blockIdx.x;
    int cnt = g_count[e];
    if (m * 128 >= cnt) return;
    extern __shared__ char smem[];
    float* As = (float*)smem;             // 128x16
    float* Bs = As + 2048;                // 16x132
    int tid = threadIdx.x;
    int tx = tid & 15, ty = tid >> 4;
    int n0 = nt * 512;
    const float* Ab = g_h + ((size_t)e * T_TOK + (size_t)m * 128) * I_DIM;
    for (int nh = 0; nh < 4; nh++) {
        float acc[4][8];
#pragma unroll
        for (int i = 0; i < 4; i++)
#pragma unroll
            for (int j = 0; j < 8; j++) acc[i][j] = 0.f;
        for (int kc = 0; kc < I_DIM / 16; kc++) {
            __syncthreads();
#pragma unroll
            for (int L = 0; L < 4; L++) {
                int f = tid + NT * L;
                int row = f >> 4, k = f & 15;
                As[f] = Ab[(size_t)row * I_DIM + kc * 16 + k];
            }
#pragma unroll
            for (int L = 0; L < 4; L++) {
                int f = tid + NT * L;
                int k = f >> 7, c = f & 127;
                Bs[k * 132 + c] = g_w2t[((size_t)e * H_DIM + n0 + nh * 128 + c) * I_DIM + kc * 16 + k];
            }
            __syncthreads();
#pragma unroll
            for (int k = 0; k < 16; k++) {
                float av[4], b[8];
#pragma unroll
                for (int i = 0; i < 4; i++) av[i] = As[(ty * 4 + i) * 16 + k];
#pragma unroll
                for (int j = 0; j < 8; j++) b[j] = Bs[k * 132 + tx * 8 + j];
#pragma unroll
                for (int i = 0; i < 4; i++)
#pragma unroll
                    for (int j = 0; j < 8; j++) acc[i][j] += av[i] * b[j];
            }
        }
#pragma unroll
        for (int i = 0; i < 4; i++) {
            int row = ty * 4 + i, grow = m * 128 + row;
            if (grow < cnt) {
                int tok = g_tok[e * T_TOK + grow];
                float wt = g_wt[e * T_TOK + grow];
                float* orow = out + (size_t)tok * H_DIM + n0 + nh * 128 + tx * 8;
#pragma unroll
                for (int j = 0; j < 8; j++)
                    atomicAdd(&orow[j], wt * acc[i][j]);
            }
        }
    }
#endif
}

// ---------------- launch ----------------
extern "C" void kernel_launch(void* const* d_in, const int* in_sizes, int n_in,
                              void* d_out, int out_size) {
    const float* x  = (const float*)d_in[0];   // hidden_states [T,H]
    const float* gw = (const float*)d_in[1];   // gate_w [H,E]
    const float* w1 = (const float*)d_in[2];   // [E,H,I]
    const float* w3 = (const float*)d_in[3];   // [E,H,I]
    const float* w2 = (const float*)d_in[4];   // [E,I,H]
    float* out = (float*)d_out;

    cudaFuncSetAttribute(k_gemm1, cudaFuncAttributeMaxDynamicSharedMemorySize, S1_SMEM);
    cudaFuncSetAttribute(k_gemm2, cudaFuncAttributeMaxDynamicSharedMemorySize, S2_SMEM);

    k_zero<<<T_TOK * H_DIM / 4 / 256, 256>>>(out);
    k_gate<<<T_TOK, 256>>>(x, gw);
    k_tr13<<<dim3(I_DIM / 32, H_DIM / 32, 2 * E_NUM), 256>>>(w1, w3);
    k_tr2 <<<dim3(H_DIM / 32, I_DIM / 32, E_NUM), 256>>>(w2);
    k_pack<<<dim3(T_TOK / 8, E_NUM), 256>>>(x);
    k_gemm1<<<dim3(T_TOK / 128, I_DIM / 256, E_NUM), NT, S1_SMEM>>>();
    k_gemm2<<<dim3(T_TOK / 128, H_DIM / 512, E_NUM), NT, S2_SMEM>>>(out);
}